// round 3
// baseline (speedup 1.0000x reference)
#include <cuda_runtime.h>
#include <math.h>

// Problem constants
#define TT    512
#define TOPK  2
#define NE    8
#define NH    2816
#define ND    1024
#define NPAIR (TT * TOPK)   // 1024

// Tile config
#define TM 64
#define TN 64
#define TK 16

// Scratch (static __device__ allocations are the sanctioned scratch mechanism)
__device__ int   d_cnt[NE];
__device__ int   d_slot[NE][NPAIR];          // pair index p = t*TOPK + k, grouped by expert
__device__ float d_G[(size_t)NPAIR * NH];    // gated hidden activations, 11.5 MB

// ---------------------------------------------------------------------------
// Routing: bucket the 1024 (token, k) pairs by expert.
// NOTE: expert_indices is int32 (JAX default, x64 disabled despite jnp.int64).
// ---------------------------------------------------------------------------
__global__ void route_kernel(const int* __restrict__ eidx) {
    __shared__ int s_cnt[NE];
    int tid = threadIdx.x;
    if (tid < NE) s_cnt[tid] = 0;
    __syncthreads();
    int e = eidx[tid];                    // 0..7
    int slot = atomicAdd(&s_cnt[e], 1);
    d_slot[e][slot] = tid;                // tid == pair index p
    __syncthreads();
    if (tid < NE) d_cnt[tid] = s_cnt[tid];
}

__device__ __forceinline__ float siluf(float v) {
    return v / (1.0f + expf(-v));
}

// ---------------------------------------------------------------------------
// GEMM1: for expert e, rows = gathered tokens, G[p, h] = silu(x.w1) * (x.w3)
// A (M x K=1024) gathered from x; B1/B3 = w1/w3[e] (N=2816 rows, K-contiguous).
// Both operands K-contiguous ("NT" gemm). Shares the A tile between w1 and w3.
// ---------------------------------------------------------------------------
__global__ __launch_bounds__(256) void gemm1_kernel(
    const float* __restrict__ x,
    const float* __restrict__ w1,
    const float* __restrict__ w3)
{
    int e    = blockIdx.z;
    int cnt  = d_cnt[e];
    int row0 = blockIdx.y * TM;
    if (row0 >= cnt) return;
    int col0 = blockIdx.x * TN;

    __shared__ float sA[TM][TK];        // [m][k]
    __shared__ float sB1[TK][TN];       // [k][n] (transposed on store)
    __shared__ float sB3[TK][TN];
    __shared__ int   s_p[TM];           // pair index per row
    __shared__ int   s_tok[TM];         // token index per row

    int tx  = threadIdx.x;              // 0..15 (cols)
    int ty  = threadIdx.y;              // 0..15 (rows)
    int tid = ty * 16 + tx;

    if (tid < TM) {
        int r = row0 + tid;
        int p = (r < cnt) ? d_slot[e][r] : d_slot[e][0];  // clamp; garbage rows never stored
        s_p[tid]   = p;
        s_tok[tid] = p >> 1;            // TOPK == 2
    }
    __syncthreads();

    float acc1[4][4] = {};
    float acc3[4][4] = {};

    int lm = tid >> 2;                  // 0..63 row within tile
    int lk = (tid & 3) * 4;             // 0,4,8,12
    const float* w1base = w1 + ((size_t)e * NH + col0) * ND;
    const float* w3base = w3 + ((size_t)e * NH + col0) * ND;
    const float* xrow   = x + (size_t)s_tok[lm] * ND + lk;
    const float* w1row  = w1base + (size_t)lm * ND + lk;
    const float* w3row  = w3base + (size_t)lm * ND + lk;

    for (int k0 = 0; k0 < ND; k0 += TK) {
        float4 av  = *(const float4*)(xrow  + k0);
        float4 b1v = *(const float4*)(w1row + k0);
        float4 b3v = *(const float4*)(w3row + k0);

        *(float4*)&sA[lm][lk] = av;
        sB1[lk + 0][lm] = b1v.x; sB1[lk + 1][lm] = b1v.y;
        sB1[lk + 2][lm] = b1v.z; sB1[lk + 3][lm] = b1v.w;
        sB3[lk + 0][lm] = b3v.x; sB3[lk + 1][lm] = b3v.y;
        sB3[lk + 2][lm] = b3v.z; sB3[lk + 3][lm] = b3v.w;
        __syncthreads();

        #pragma unroll
        for (int kk = 0; kk < TK; kk++) {
            float a0 = sA[ty * 4 + 0][kk];
            float a1 = sA[ty * 4 + 1][kk];
            float a2 = sA[ty * 4 + 2][kk];
            float a3 = sA[ty * 4 + 3][kk];
            float4 b1 = *(const float4*)&sB1[kk][tx * 4];
            float4 b3 = *(const float4*)&sB3[kk][tx * 4];

            acc1[0][0] += a0 * b1.x; acc1[0][1] += a0 * b1.y; acc1[0][2] += a0 * b1.z; acc1[0][3] += a0 * b1.w;
            acc1[1][0] += a1 * b1.x; acc1[1][1] += a1 * b1.y; acc1[1][2] += a1 * b1.z; acc1[1][3] += a1 * b1.w;
            acc1[2][0] += a2 * b1.x; acc1[2][1] += a2 * b1.y; acc1[2][2] += a2 * b1.z; acc1[2][3] += a2 * b1.w;
            acc1[3][0] += a3 * b1.x; acc1[3][1] += a3 * b1.y; acc1[3][2] += a3 * b1.z; acc1[3][3] += a3 * b1.w;

            acc3[0][0] += a0 * b3.x; acc3[0][1] += a0 * b3.y; acc3[0][2] += a0 * b3.z; acc3[0][3] += a0 * b3.w;
            acc3[1][0] += a1 * b3.x; acc3[1][1] += a1 * b3.y; acc3[1][2] += a1 * b3.z; acc3[1][3] += a1 * b3.w;
            acc3[2][0] += a2 * b3.x; acc3[2][1] += a2 * b3.y; acc3[2][2] += a2 * b3.z; acc3[2][3] += a2 * b3.w;
            acc3[3][0] += a3 * b3.x; acc3[3][1] += a3 * b3.y; acc3[3][2] += a3 * b3.z; acc3[3][3] += a3 * b3.w;
        }
        __syncthreads();
    }

    // Epilogue: gate + scatter to G (rows keyed by global pair index p)
    #pragma unroll
    for (int i = 0; i < 4; i++) {
        int r = row0 + ty * 4 + i;
        if (r < cnt) {
            int p = s_p[ty * 4 + i];
            float4 g;
            g.x = siluf(acc1[i][0]) * acc3[i][0];
            g.y = siluf(acc1[i][1]) * acc3[i][1];
            g.z = siluf(acc1[i][2]) * acc3[i][2];
            g.w = siluf(acc1[i][3]) * acc3[i][3];
            *(float4*)&d_G[(size_t)p * NH + col0 + tx * 4] = g;
        }
    }
}

// ---------------------------------------------------------------------------
// GEMM2: out[p, i] = sum_h G[p, h] * w2[e, h, i]   ("NN" gemm, K = H = 2816)
// ---------------------------------------------------------------------------
__global__ __launch_bounds__(256) void gemm2_kernel(
    const float* __restrict__ w2,
    float* __restrict__ out)
{
    int e    = blockIdx.z;
    int cnt  = d_cnt[e];
    int row0 = blockIdx.y * TM;
    if (row0 >= cnt) return;
    int col0 = blockIdx.x * TN;

    __shared__ float sA[TM][TK];        // [m][k]
    __shared__ float sB[TK][TN];        // [k][n], natural layout (i contiguous)
    __shared__ int   s_p[TM];

    int tx  = threadIdx.x;
    int ty  = threadIdx.y;
    int tid = ty * 16 + tx;

    if (tid < TM) {
        int r = row0 + tid;
        s_p[tid] = (r < cnt) ? d_slot[e][r] : d_slot[e][0];
    }
    __syncthreads();

    float acc[4][4] = {};

    int lm = tid >> 2;                  // A tile: row, 0..63
    int lk = (tid & 3) * 4;             // A tile: k, 0..12
    int bk = tid >> 4;                  // B tile: k row, 0..15
    int bn = (tid & 15) * 4;            // B tile: n col, 0..60
    const float* grow  = d_G + (size_t)s_p[lm] * NH + lk;
    const float* w2row = w2 + ((size_t)e * NH + bk) * ND + col0 + bn;

    for (int k0 = 0; k0 < NH; k0 += TK) {
        float4 av = *(const float4*)(grow + k0);
        float4 bv = *(const float4*)(w2row + (size_t)k0 * ND);

        *(float4*)&sA[lm][lk] = av;
        *(float4*)&sB[bk][bn] = bv;
        __syncthreads();

        #pragma unroll
        for (int kk = 0; kk < TK; kk++) {
            float a0 = sA[ty * 4 + 0][kk];
            float a1 = sA[ty * 4 + 1][kk];
            float a2 = sA[ty * 4 + 2][kk];
            float a3 = sA[ty * 4 + 3][kk];
            float4 b = *(const float4*)&sB[kk][tx * 4];

            acc[0][0] += a0 * b.x; acc[0][1] += a0 * b.y; acc[0][2] += a0 * b.z; acc[0][3] += a0 * b.w;
            acc[1][0] += a1 * b.x; acc[1][1] += a1 * b.y; acc[1][2] += a1 * b.z; acc[1][3] += a1 * b.w;
            acc[2][0] += a2 * b.x; acc[2][1] += a2 * b.y; acc[2][2] += a2 * b.z; acc[2][3] += a2 * b.w;
            acc[3][0] += a3 * b.x; acc[3][1] += a3 * b.y; acc[3][2] += a3 * b.z; acc[3][3] += a3 * b.w;
        }
        __syncthreads();
    }

    #pragma unroll
    for (int i = 0; i < 4; i++) {
        int r = row0 + ty * 4 + i;
        if (r < cnt) {
            int p = s_p[ty * 4 + i];
            float4 o;
            o.x = acc[i][0]; o.y = acc[i][1]; o.z = acc[i][2]; o.w = acc[i][3];
            *(float4*)&out[(size_t)p * ND + col0 + tx * 4] = o;
        }
    }
}

// ---------------------------------------------------------------------------
extern "C" void kernel_launch(void* const* d_in, const int* in_sizes, int n_in,
                              void* d_out, int out_size) {
    const float* x    = (const float*)d_in[0];
    const int*   eidx = (const int*)d_in[1];     // int32 (JAX default int)
    const float* w1   = (const float*)d_in[2];
    const float* w2   = (const float*)d_in[3];
    const float* w3   = (const float*)d_in[4];
    float*       out  = (float*)d_out;

    route_kernel<<<1, NPAIR>>>(eidx);

    dim3 blk(16, 16);
    dim3 g1(NH / TN, (NPAIR + TM - 1) / TM, NE);   // 44 x 16 x 8
    gemm1_kernel<<<g1, blk>>>(x, w1, w3);

    dim3 g2(ND / TN, (NPAIR + TM - 1) / TM, NE);   // 16 x 16 x 8
    gemm2_kernel<<<g2, blk>>>(w2, out);
}

// round 5
// speedup vs baseline: 2.0158x; 2.0158x over previous
#include <cuda_runtime.h>
#include <cuda_bf16.h>
#include <math.h>
#include <stdint.h>

#define TT    512
#define TOPK  2
#define NE    8
#define NH    2816
#define ND    1024
#define NPAIR 1024

// Scratch (__device__ globals are the sanctioned scratch mechanism)
__device__ int d_cnt[NE];
__device__ int d_slot[NE][NPAIR];
__device__ __align__(16) float          d_H1[(size_t)NPAIR * NH];   // x.w1 raw
__device__ __align__(16) float          d_H3[(size_t)NPAIR * NH];   // x.w3 raw
__device__ __align__(16) __nv_bfloat16  d_Ghi[(size_t)NPAIR * NH];  // gated, hi
__device__ __align__(16) __nv_bfloat16  d_Glo[(size_t)NPAIR * NH];  // gated, lo
__device__ __align__(16) __nv_bfloat16  d_xhi[TT * ND];
__device__ __align__(16) __nv_bfloat16  d_xlo[TT * ND];

// ---------------------------------------------------------------------------
__device__ __forceinline__ uint32_t smem_u32(const void* p) {
    uint32_t a;
    asm("{ .reg .u64 t; cvta.to.shared.u64 t, %1; cvt.u32.u64 %0, t; }" : "=r"(a) : "l"(p));
    return a;
}
__device__ __forceinline__ void ldsm4(uint32_t* r, uint32_t addr) {
    asm volatile("ldmatrix.sync.aligned.m8n8.x4.shared.b16 {%0,%1,%2,%3}, [%4];"
        : "=r"(r[0]), "=r"(r[1]), "=r"(r[2]), "=r"(r[3]) : "r"(addr));
}
__device__ __forceinline__ void mma16816(float* c, const uint32_t* a, const uint32_t* b) {
    asm volatile("mma.sync.aligned.m16n8k16.row.col.f32.bf16.bf16.f32 "
        "{%0,%1,%2,%3},{%4,%5,%6,%7},{%8,%9},{%0,%1,%2,%3};"
        : "+f"(c[0]), "+f"(c[1]), "+f"(c[2]), "+f"(c[3])
        : "r"(a[0]), "r"(a[1]), "r"(a[2]), "r"(a[3]), "r"(b[0]), "r"(b[1]));
}
__device__ __forceinline__ uint32_t pack2(__nv_bfloat16 e0, __nv_bfloat16 e1) {
    return (uint32_t)__bfloat16_as_ushort(e0) | ((uint32_t)__bfloat16_as_ushort(e1) << 16);
}
// split float v -> hi bf16, lo bf16 (residual)
__device__ __forceinline__ void split_bf(float v, __nv_bfloat16& h, __nv_bfloat16& l) {
    h = __float2bfloat16(v);
    l = __float2bfloat16(v - __bfloat162float(h));
}

// ---------------------------------------------------------------------------
__global__ void route_kernel(const int* __restrict__ eidx) {
    __shared__ int s_cnt[NE];
    int tid = threadIdx.x;
    if (tid < NE) s_cnt[tid] = 0;
    __syncthreads();
    int e = eidx[tid];
    int slot = atomicAdd(&s_cnt[e], 1);
    d_slot[e][slot] = tid;
    __syncthreads();
    if (tid < NE) d_cnt[tid] = s_cnt[tid];
}

__global__ void prep_x(const float* __restrict__ x) {
    size_t i = ((size_t)blockIdx.x * blockDim.x + threadIdx.x) * 4;
    float4 v = *(const float4*)(x + i);
    __nv_bfloat16 h0, h1, h2, h3, l0, l1, l2, l3;
    split_bf(v.x, h0, l0); split_bf(v.y, h1, l1);
    split_bf(v.z, h2, l2); split_bf(v.w, h3, l3);
    uint2 hv = make_uint2(pack2(h0, h1), pack2(h2, h3));
    uint2 lv = make_uint2(pack2(l0, l1), pack2(l2, l3));
    *(uint2*)(d_xhi + i) = hv;
    *(uint2*)(d_xlo + i) = lv;
}

__global__ void gate_kernel() {
    size_t i = ((size_t)blockIdx.x * blockDim.x + threadIdx.x) * 4;
    float4 v1 = *(const float4*)(d_H1 + i);
    float4 v3 = *(const float4*)(d_H3 + i);
    float g0 = __fdividef(v1.x, 1.0f + __expf(-v1.x)) * v3.x;
    float g1 = __fdividef(v1.y, 1.0f + __expf(-v1.y)) * v3.y;
    float g2 = __fdividef(v1.z, 1.0f + __expf(-v1.z)) * v3.z;
    float g3 = __fdividef(v1.w, 1.0f + __expf(-v1.w)) * v3.w;
    __nv_bfloat16 h0, h1, h2, h3, l0, l1, l2, l3;
    split_bf(g0, h0, l0); split_bf(g1, h1, l1);
    split_bf(g2, h2, l2); split_bf(g3, h3, l3);
    *(uint2*)(d_Ghi + i) = make_uint2(pack2(h0, h1), pack2(h2, h3));
    *(uint2*)(d_Glo + i) = make_uint2(pack2(l0, l1), pack2(l2, l3));
}

// ---------------------------------------------------------------------------
// GEMM1: C[128 pairs x 128 h] = x_gathered . w{1|3}^T  (K = 1024, 16 chunks of 64)
// A = xhi/xlo bf16 (pre-split), B = w fp32 -> bf16 hi/lo inline.
// SMEM: s_p[128] | s_tok[128] | AH(16K) AL(16K) BH(16K) BL(16K)
// ---------------------------------------------------------------------------
#define G1_SMEM (1024 + 4 * 16384)

__global__ __launch_bounds__(256) void gemm1_mma(
    const float* __restrict__ w1, const float* __restrict__ w3)
{
    int z = blockIdx.z, e = z >> 1, f = z & 1;
    int cnt = d_cnt[e];
    int trow0 = blockIdx.y * 128;
    if (trow0 >= cnt) return;
    int col0 = blockIdx.x * 128;
    const float* w = f ? w3 : w1;
    float* dH = f ? d_H3 : d_H1;

    extern __shared__ char smem[];
    int* s_p   = (int*)smem;
    int* s_tok = (int*)(smem + 512);
    char* tAH = smem + 1024;
    char* tAL = tAH + 16384;
    char* tBH = tAL + 16384;
    char* tBL = tBH + 16384;
    uint32_t uAH = smem_u32(tAH), uAL = smem_u32(tAL);
    uint32_t uBH = smem_u32(tBH), uBL = smem_u32(tBL);

    int tid = threadIdx.x, lane = tid & 31, wid = tid >> 5;
    if (tid < 128) {
        int r = trow0 + tid;
        int p = (r < cnt) ? d_slot[e][r] : d_slot[e][0];
        s_p[tid] = p; s_tok[tid] = p >> 1;
    }
    __syncthreads();

    // loader: each thread owns (row = tid>>1, k-half = tid&1 -> 32 elems)
    int lrow = tid >> 1, lhalf = tid & 1;
    uint32_t swz = (uint32_t)((lrow & 7) << 4);
    const __nv_bfloat16* xh = d_xhi + (size_t)s_tok[lrow] * ND + lhalf * 32;
    const __nv_bfloat16* xl = d_xlo + (size_t)s_tok[lrow] * ND + lhalf * 32;
    const float* wrow = w + ((size_t)e * NH + col0 + lrow) * ND + lhalf * 32;

    float acc[2][8][4];
    #pragma unroll
    for (int a = 0; a < 2; a++)
        #pragma unroll
        for (int b = 0; b < 8; b++)
            #pragma unroll
            for (int c = 0; c < 4; c++) acc[a][b][c] = 0.0f;

    uint4 ra[4], rl[4];
    float4 rb[8];
    #pragma unroll
    for (int j = 0; j < 4; j++) {
        ra[j] = ((const uint4*)xh)[j];
        rl[j] = ((const uint4*)xl)[j];
    }
    #pragma unroll
    for (int j = 0; j < 8; j++) rb[j] = *(const float4*)(wrow + 4 * j);

    int wm = wid & 3, wn = wid >> 2;

    #pragma unroll 1
    for (int kc = 0; kc < 16; kc++) {
        // stage A (already bf16)
        #pragma unroll
        for (int j = 0; j < 4; j++) {
            uint32_t b = (uint32_t)(lhalf * 64 + j * 16);
            *(uint4*)(tAH + lrow * 128 + (b ^ swz)) = ra[j];
            *(uint4*)(tAL + lrow * 128 + (b ^ swz)) = rl[j];
        }
        // stage B (convert fp32 -> hi/lo)
        #pragma unroll
        for (int j = 0; j < 8; j++) {
            float4 v = rb[j];
            __nv_bfloat16 h0, h1, h2, h3, l0, l1, l2, l3;
            split_bf(v.x, h0, l0); split_bf(v.y, h1, l1);
            split_bf(v.z, h2, l2); split_bf(v.w, h3, l3);
            uint32_t b = (uint32_t)(lhalf * 64 + j * 8);
            uint32_t o0 = lrow * 128 + (b ^ swz);
            uint32_t o1 = o0 + 4;
            *(uint32_t*)(tBH + o0) = pack2(h0, h1);
            *(uint32_t*)(tBH + o1) = pack2(h2, h3);
            *(uint32_t*)(tBL + o0) = pack2(l0, l1);
            *(uint32_t*)(tBL + o1) = pack2(l2, l3);
        }
        __syncthreads();
        // prefetch next chunk (overlaps with MMA below)
        if (kc < 15) {
            #pragma unroll
            for (int j = 0; j < 4; j++) {
                ra[j] = ((const uint4*)(xh + (kc + 1) * 64))[j];
                rl[j] = ((const uint4*)(xl + (kc + 1) * 64))[j];
            }
            #pragma unroll
            for (int j = 0; j < 8; j++)
                rb[j] = *(const float4*)(wrow + (kc + 1) * 64 + 4 * j);
        }
        // MMA over 4 k16 steps
        #pragma unroll
        for (int ks = 0; ks < 4; ks++) {
            uint32_t Ah[2][4], Al[2][4], Bh[4][4], Bl[4][4];
            int kb = ks * 32;
            #pragma unroll
            for (int mi = 0; mi < 2; mi++) {
                int row = wm * 32 + mi * 16 + (lane & 15);
                uint32_t b = (uint32_t)(kb + ((lane >> 4) << 4));
                uint32_t off = (uint32_t)row * 128 + (b ^ (uint32_t)((row & 7) << 4));
                ldsm4(Ah[mi], uAH + off);
                ldsm4(Al[mi], uAL + off);
            }
            #pragma unroll
            for (int nb = 0; nb < 4; nb++) {
                int row = wn * 64 + nb * 16 + (lane & 7) + (((lane >> 4) & 1) << 3);
                uint32_t b = (uint32_t)(kb + (((lane >> 3) & 1) << 4));
                uint32_t off = (uint32_t)row * 128 + (b ^ (uint32_t)((row & 7) << 4));
                ldsm4(Bh[nb], uBH + off);
                ldsm4(Bl[nb], uBL + off);
            }
            #pragma unroll
            for (int mi = 0; mi < 2; mi++)
                #pragma unroll
                for (int nb = 0; nb < 4; nb++) {
                    mma16816(acc[mi][2 * nb],     Ah[mi], &Bh[nb][0]);
                    mma16816(acc[mi][2 * nb],     Ah[mi], &Bl[nb][0]);
                    mma16816(acc[mi][2 * nb],     Al[mi], &Bh[nb][0]);
                    mma16816(acc[mi][2 * nb + 1], Ah[mi], &Bh[nb][2]);
                    mma16816(acc[mi][2 * nb + 1], Ah[mi], &Bl[nb][2]);
                    mma16816(acc[mi][2 * nb + 1], Al[mi], &Bh[nb][2]);
                }
        }
        __syncthreads();
    }

    // epilogue: C[row=pair, col=h] -> dH (predicated rows)
    int cntLoc = cnt - trow0; if (cntLoc > 128) cntLoc = 128;
    #pragma unroll
    for (int mi = 0; mi < 2; mi++) {
        int r0 = wm * 32 + mi * 16 + (lane >> 2);
        int r1 = r0 + 8;
        #pragma unroll
        for (int ni = 0; ni < 8; ni++) {
            int col = col0 + wn * 64 + ni * 8 + (lane & 3) * 2;
            if (r0 < cntLoc) {
                float2 v = make_float2(acc[mi][ni][0], acc[mi][ni][1]);
                *(float2*)&dH[(size_t)s_p[r0] * NH + col] = v;
            }
            if (r1 < cntLoc) {
                float2 v = make_float2(acc[mi][ni][2], acc[mi][ni][3]);
                *(float2*)&dH[(size_t)s_p[r1] * NH + col] = v;
            }
        }
    }
}

// ---------------------------------------------------------------------------
// GEMM2: C[128 pairs x 64 d] = G . w2  (K = NH = 2816, 44 chunks of 64)
// A = Ghi/Glo bf16 (pre-split, K-contig). B = w2 fp32, transposed to K-major
// during the conversion store.
// SMEM: s_p[128] | AH(16K) AL(16K) BH(8K) BL(8K)
// ---------------------------------------------------------------------------
#define G2_SMEM (1024 + 2 * 16384 + 2 * 8192)

__global__ __launch_bounds__(256) void gemm2_mma(
    const float* __restrict__ w2, float* __restrict__ out)
{
    int e = blockIdx.z;
    int cnt = d_cnt[e];
    int trow0 = blockIdx.y * 128;
    if (trow0 >= cnt) return;
    int col0 = blockIdx.x * 64;

    extern __shared__ char smem[];
    int* s_p = (int*)smem;
    char* tAH = smem + 1024;
    char* tAL = tAH + 16384;
    char* tBH = tAL + 16384;
    char* tBL = tBH + 8192;
    uint32_t uAH = smem_u32(tAH), uAL = smem_u32(tAL);
    uint32_t uBH = smem_u32(tBH), uBL = smem_u32(tBL);

    int tid = threadIdx.x, lane = tid & 31, wid = tid >> 5;
    if (tid < 128) {
        int r = trow0 + tid;
        s_p[tid] = (r < cnt) ? d_slot[e][r] : d_slot[e][0];
    }
    __syncthreads();

    // A loader
    int lrow = tid >> 1, lhalf = tid & 1;
    uint32_t swzA = (uint32_t)((lrow & 7) << 4);
    const __nv_bfloat16* gh = d_Ghi + (size_t)s_p[lrow] * NH + lhalf * 32;
    const __nv_bfloat16* gl = d_Glo + (size_t)s_p[lrow] * NH + lhalf * 32;
    // B loader: h-pair + 8 d's per thread
    int hpair = tid & 31, h = hpair * 2;
    int d0 = (tid >> 5) * 8;
    const float* bp = w2 + ((size_t)e * NH + h) * ND + col0 + d0;

    float acc[2][4][4];
    #pragma unroll
    for (int a = 0; a < 2; a++)
        #pragma unroll
        for (int b = 0; b < 4; b++)
            #pragma unroll
            for (int c = 0; c < 4; c++) acc[a][b][c] = 0.0f;

    uint4 ra[4], rl[4];
    float4 rb0[2], rb1[2];
    #pragma unroll
    for (int j = 0; j < 4; j++) {
        ra[j] = ((const uint4*)gh)[j];
        rl[j] = ((const uint4*)gl)[j];
    }
    #pragma unroll
    for (int j = 0; j < 2; j++) {
        rb0[j] = *(const float4*)(bp + 4 * j);
        rb1[j] = *(const float4*)(bp + ND + 4 * j);
    }

    int wm = wid & 3, wn = wid >> 2;

    #pragma unroll 1
    for (int kc = 0; kc < 44; kc++) {
        // stage A
        #pragma unroll
        for (int j = 0; j < 4; j++) {
            uint32_t b = (uint32_t)(lhalf * 64 + j * 16);
            *(uint4*)(tAH + lrow * 128 + (b ^ swzA)) = ra[j];
            *(uint4*)(tAL + lrow * 128 + (b ^ swzA)) = rl[j];
        }
        // stage B (transpose: element (d, h) at byte d*128 + 2h, pair-packed)
        #pragma unroll
        for (int j = 0; j < 2; j++) {
            float va[4] = { rb0[j].x, rb0[j].y, rb0[j].z, rb0[j].w };
            float vb[4] = { rb1[j].x, rb1[j].y, rb1[j].z, rb1[j].w };
            #pragma unroll
            for (int m = 0; m < 4; m++) {
                int d = d0 + 4 * j + m;
                uint32_t off = (uint32_t)d * 128 +
                    (((uint32_t)(h * 2)) ^ (uint32_t)((d & 7) << 4));
                __nv_bfloat16 ha, la, hb, lb;
                split_bf(va[m], ha, la);
                split_bf(vb[m], hb, lb);
                *(uint32_t*)(tBH + off) = pack2(ha, hb);
                *(uint32_t*)(tBL + off) = pack2(la, lb);
            }
        }
        __syncthreads();
        if (kc < 43) {
            #pragma unroll
            for (int j = 0; j < 4; j++) {
                ra[j] = ((const uint4*)(gh + (kc + 1) * 64))[j];
                rl[j] = ((const uint4*)(gl + (kc + 1) * 64))[j];
            }
            const float* bpn = bp + (size_t)(kc + 1) * 64 * ND;
            #pragma unroll
            for (int j = 0; j < 2; j++) {
                rb0[j] = *(const float4*)(bpn + 4 * j);
                rb1[j] = *(const float4*)(bpn + ND + 4 * j);
            }
        }
        #pragma unroll
        for (int ks = 0; ks < 4; ks++) {
            uint32_t Ah[2][4], Al[2][4], Bh[2][4], Bl[2][4];
            int kb = ks * 32;
            #pragma unroll
            for (int mi = 0; mi < 2; mi++) {
                int row = wm * 32 + mi * 16 + (lane & 15);
                uint32_t b = (uint32_t)(kb + ((lane >> 4) << 4));
                uint32_t off = (uint32_t)row * 128 + (b ^ (uint32_t)((row & 7) << 4));
                ldsm4(Ah[mi], uAH + off);
                ldsm4(Al[mi], uAL + off);
            }
            #pragma unroll
            for (int nb = 0; nb < 2; nb++) {
                int row = wn * 32 + nb * 16 + (lane & 7) + (((lane >> 4) & 1) << 3);
                uint32_t b = (uint32_t)(kb + (((lane >> 3) & 1) << 4));
                uint32_t off = (uint32_t)row * 128 + (b ^ (uint32_t)((row & 7) << 4));
                ldsm4(Bh[nb], uBH + off);
                ldsm4(Bl[nb], uBL + off);
            }
            #pragma unroll
            for (int mi = 0; mi < 2; mi++)
                #pragma unroll
                for (int nb = 0; nb < 2; nb++) {
                    mma16816(acc[mi][2 * nb],     Ah[mi], &Bh[nb][0]);
                    mma16816(acc[mi][2 * nb],     Ah[mi], &Bl[nb][0]);
                    mma16816(acc[mi][2 * nb],     Al[mi], &Bh[nb][0]);
                    mma16816(acc[mi][2 * nb + 1], Ah[mi], &Bh[nb][2]);
                    mma16816(acc[mi][2 * nb + 1], Ah[mi], &Bl[nb][2]);
                    mma16816(acc[mi][2 * nb + 1], Al[mi], &Bh[nb][2]);
                }
        }
        __syncthreads();
    }

    int cntLoc = cnt - trow0; if (cntLoc > 128) cntLoc = 128;
    #pragma unroll
    for (int mi = 0; mi < 2; mi++) {
        int r0 = wm * 32 + mi * 16 + (lane >> 2);
        int r1 = r0 + 8;
        #pragma unroll
        for (int ni = 0; ni < 4; ni++) {
            int col = col0 + wn * 32 + ni * 8 + (lane & 3) * 2;
            if (r0 < cntLoc) {
                float2 v = make_float2(acc[mi][ni][0], acc[mi][ni][1]);
                *(float2*)&out[(size_t)s_p[r0] * ND + col] = v;
            }
            if (r1 < cntLoc) {
                float2 v = make_float2(acc[mi][ni][2], acc[mi][ni][3]);
                *(float2*)&out[(size_t)s_p[r1] * ND + col] = v;
            }
        }
    }
}

// ---------------------------------------------------------------------------
extern "C" void kernel_launch(void* const* d_in, const int* in_sizes, int n_in,
                              void* d_out, int out_size) {
    const float* x    = (const float*)d_in[0];
    const int*   eidx = (const int*)d_in[1];   // int32 (JAX default int)
    const float* w1   = (const float*)d_in[2];
    const float* w2   = (const float*)d_in[3];
    const float* w3   = (const float*)d_in[4];
    float*       out  = (float*)d_out;

    static bool attr_done = false;
    if (!attr_done) {
        cudaFuncSetAttribute(gemm1_mma, cudaFuncAttributeMaxDynamicSharedMemorySize, G1_SMEM);
        cudaFuncSetAttribute(gemm2_mma, cudaFuncAttributeMaxDynamicSharedMemorySize, G2_SMEM);
        attr_done = true;
    }

    route_kernel<<<1, NPAIR>>>(eidx);
    prep_x<<<(TT * ND / 4) / 256, 256>>>(x);

    dim3 g1(NH / 128, NPAIR / 128, NE * 2);   // 22 x 8 x 16
    gemm1_mma<<<g1, 256, G1_SMEM>>>(w1, w3);

    gate_kernel<<<(int)(((size_t)NPAIR * NH / 4) / 256), 256>>>();

    dim3 g2(ND / 64, NPAIR / 128, NE);        // 16 x 8 x 8
    gemm2_mma<<<g2, 256, G2_SMEM>>>(w2, out);
}